// round 16
// baseline (speedup 1.0000x reference)
#include <cuda_runtime.h>
#include <cuda_fp16.h>
#include <cstdint>

// Problem constants
#define G 8
#define T 4096
#define H 2048
#define E 64
#define GT (G*T)              // 32768 tokens

// Output layout (float32, concatenated in reference return order)
#define DI_OFF 0              // dispatch_indices [G,T,2,2] -> 131072
#define CW_OFF 131072         // combine_weights  [G,T,2]   -> 65536
#define AUX_OFF 196608        // scalar
#define P_OFF 196609          // router_probs [G,T,64] -> 2097152
#define Z_OFF 2293761         // scalar

// K1 tiling
#define KB 64                 // k-elems per chunk (128B fp16 rows)
#define NCH (H/KB)            // 32 chunks
#define TM 128                // tokens per CTA
#define NCTA (GT/TM)          // 256 CTAs
#define NTHR 320              // 256 consumer + 64 producer threads

// K1 dynamic smem byte offsets
#define SO_BS   0                       // bias, 64 floats
#define SO_ZRED 256                     // 4 floats
#define SO_A1   1024                    // x hi limb: 2 bufs x 16KB
#define SO_A2   (SO_A1 + 32768)         // x lo limb (scaled 2^11): 2 bufs x 16KB
#define SO_B1   (SO_A2 + 32768)         // w hi limb: 2 bufs x 8KB
#define SO_B2   (SO_B1 + 16384)         // w lo limb (scaled 2^11): 2 bufs x 8KB
#define SMEM_TOTAL (SO_B2 + 16384)      // 99328 bytes
#define SO_LS   1024                    // epilogue overlay: 128 x 68 floats

#define CORR_SCALE (1.0f/2048.0f)

// -------- scratch (device globals; no allocation allowed) --------
__device__ float g_gate0[GT];
__device__ float g_gate1[GT];
__device__ int   g_e0[GT];
__device__ int   g_e1[GT];
__device__ int   g_sorted[GT];   // packed: tok | e0<<12 | e1<<18 (rank order)
__device__ int   g_prio0[GT];
__device__ int   g_prio1[GT];
__device__ float g_zpart[NCTA];
__device__ int   g_cnt[G*E];
__device__ float g_psum2[NCTA*E];   // per-CTA prob sums (deterministic)
__device__ __half g_w1[E*H];   // W^T hi limb [expert][k]
__device__ __half g_w2[E*H];   // W^T lo limb, scaled by 2^11
__device__ int   g_seghist[64*64];  // per (group,segment) expert totals
__device__ int   g_segflag[64];     // lookback flags

__device__ __forceinline__ uint32_t smem_u32(const void* p) {
    uint32_t a;
    asm("{ .reg .u64 t; cvta.to.shared.u64 t, %1; cvt.u32.u64 %0, t; }"
        : "=r"(a) : "l"(p));
    return a;
}
__device__ __forceinline__ void ldsm4(uint32_t* r, uint32_t a) {
    asm volatile("ldmatrix.sync.aligned.m8n8.x4.shared.b16 {%0,%1,%2,%3}, [%4];"
        : "=r"(r[0]), "=r"(r[1]), "=r"(r[2]), "=r"(r[3]) : "r"(a));
}
__device__ __forceinline__ void mma16816(float* c, const uint32_t* a, const uint32_t* b) {
    asm volatile("mma.sync.aligned.m16n8k16.row.col.f32.f16.f16.f32 "
        "{%0,%1,%2,%3}, {%4,%5,%6,%7}, {%8,%9}, {%0,%1,%2,%3};"
        : "+f"(c[0]), "+f"(c[1]), "+f"(c[2]), "+f"(c[3])
        : "r"(a[0]), "r"(a[1]), "r"(a[2]), "r"(a[3]), "r"(b[0]), "r"(b[1]));
}
__device__ __forceinline__ void mma16816h(uint32_t* c, const uint32_t* a, const uint32_t* b) {
    asm volatile("mma.sync.aligned.m16n8k16.row.col.f16.f16.f16.f16 "
        "{%0,%1}, {%2,%3,%4,%5}, {%6,%7}, {%0,%1};"
        : "+r"(c[0]), "+r"(c[1])
        : "r"(a[0]), "r"(a[1]), "r"(a[2]), "r"(a[3]), "r"(b[0]), "r"(b[1]));
}
__device__ __forceinline__ uint32_t h2u(__half2 h) {
    return *reinterpret_cast<uint32_t*>(&h);
}
__device__ __forceinline__ void cp16(uint32_t dst, const void* src) {
    asm volatile("cp.async.cg.shared.global [%0], [%1], 16;"
        :: "r"(dst), "l"(src) : "memory");
}

// ---------------- K0: zero counters/flags + preconvert W^T into fp16 limbs ----------------
__global__ __launch_bounds__(256) void k0_prep(const float* __restrict__ W) {
    int gidx = blockIdx.x * 256 + threadIdx.x;     // 128 CTAs -> 32768 threads
    if (gidx < G*E) g_cnt[gidx] = 0;
    if (gidx >= 512 && gidx < 512 + 64) g_segflag[gidx - 512] = 0;
    // H*16 float4 granules: k = gidx>>4, experts 4q..4q+3
    int k = gidx >> 4, q = gidx & 15;
    float4 v = reinterpret_cast<const float4*>(W)[gidx];
    float xs[4] = {v.x, v.y, v.z, v.w};
#pragma unroll
    for (int j = 0; j < 4; ++j) {
        int e = 4*q + j;
        __half hi = __float2half_rn(xs[j]);
        float hf = __half2float(hi);
        __half lo = __float2half_rn((xs[j] - hf) * 2048.0f);  // pre-scaled limb
        g_w1[e*H + k] = hi;
        g_w2[e*H + k] = lo;
    }
}

// ---------------- K1: warp-specialized mma.sync GEMM (2-limb fp16) ----------------
// 320 threads: warps 0-7 consumers (ldsm+MMA only), warps 8-9 producers
// (LDG X -> limb split -> STS; W limbs via cp.async). One barrier per chunk.
__global__ __launch_bounds__(NTHR, 2) void k1_gemm(
    const float* __restrict__ X, const float* __restrict__ Bv,
    float* __restrict__ out)
{
    extern __shared__ __align__(16) char smem[];
    __shared__ float psums[4][64];
    const uint32_t sb = smem_u32(smem);
    const int tid = threadIdx.x;
    const int wid = tid >> 5, lane = tid & 31;
    const int wm = wid >> 1, wn = wid & 1;          // consumers only (wid<8)
    const int tok0 = blockIdx.x * TM;
    const bool is_prod = (tid >= 256);
    const int ptid = tid - 256;                      // 0..63 for producers

    if (tid < 64) *reinterpret_cast<float*>(smem + SO_BS + tid*4) = Bv[tid];

    float acc[2][4][4];
    uint32_t acch[2][4][2];
#pragma unroll
    for (int mt = 0; mt < 2; ++mt)
#pragma unroll
        for (int nt = 0; nt < 4; ++nt) {
#pragma unroll
            for (int i = 0; i < 4; ++i) acc[mt][nt][i] = 0.f;
            acch[mt][nt][0] = 0u; acch[mt][nt][1] = 0u;
        }

    // producer: stage chunk ch into buffer buf (X limbs + W limbs)
    auto produce = [&](int ch, int buf) {
        const int hc = ch * KB;
        // B limbs first via cp.async (overlaps the X work below)
        const uint32_t B1 = sb + SO_B1 + buf*8192;
        const uint32_t B2 = sb + SO_B2 + buf*8192;
#pragma unroll
        for (int i = 0; i < 8; ++i) {
            int idx = i*64 + ptid, e = idx >> 3, g = idx & 7;
            int offs = e*128 + ((g ^ (e & 7)) << 4);
            cp16(B1 + offs, g_w1 + (size_t)e*H + hc + g*8);
            cp16(B2 + offs, g_w2 + (size_t)e*H + hc + g*8);
        }
        asm volatile("cp.async.commit_group;" ::: "memory");
        // X: 2048 float4 over 64 threads = 32 each, in 4 batches of 8
        char* A1 = smem + SO_A1 + buf*16384;
        char* A2 = smem + SO_A2 + buf*16384;
        float4 xr[8];
#pragma unroll
        for (int half = 0; half < 4; ++half) {
#pragma unroll
            for (int it = 0; it < 8; ++it) {
                int idx = (half*8 + it)*64 + ptid;
                int row = idx >> 4, q = idx & 15;
                xr[it] = *reinterpret_cast<const float4*>(
                    X + (size_t)(tok0 + row)*H + hc + q*4);
            }
#pragma unroll
            for (int it = 0; it < 8; ++it) {
                int idx = (half*8 + it)*64 + ptid;
                int row = idx >> 4, q = idx & 15;
                float4 v = xr[it];
                __half2 h01 = __floats2half2_rn(v.x, v.y);
                __half2 h23 = __floats2half2_rn(v.z, v.w);
                float2 f01 = __half22float2(h01);
                float2 f23 = __half22float2(h23);
                __half2 l01 = __floats2half2_rn((v.x - f01.x)*2048.f, (v.y - f01.y)*2048.f);
                __half2 l23 = __floats2half2_rn((v.z - f23.x)*2048.f, (v.w - f23.y)*2048.f);
                int offs = row*128 + ((((q >> 1) ^ (row & 7)) << 4) | ((q & 1) << 3));
                *reinterpret_cast<uint2*>(A1 + offs) = make_uint2(h2u(h01), h2u(h23));
                *reinterpret_cast<uint2*>(A2 + offs) = make_uint2(h2u(l01), h2u(l23));
            }
        }
        asm volatile("cp.async.wait_group 0;" ::: "memory");
    };

    auto comp_chunk = [&](int buf) {
        const uint32_t sA1 = sb + SO_A1 + buf*16384;
        const uint32_t sB1 = sb + SO_B1 + buf*8192;
#pragma unroll
        for (int ks = 0; ks < 4; ++ks) {
            const int kb = ks*2;
            uint32_t a1f[2][4], a2f[2][4], b1f[2][4], b2f[2][4];
#pragma unroll
            for (int mt = 0; mt < 2; ++mt) {
                int row = wm*32 + mt*16 + (lane & 15);
                int col = (kb + (lane >> 4)) ^ (row & 7);
                uint32_t ad = sA1 + row*128 + col*16;
                ldsm4(a1f[mt], ad);
                ldsm4(a2f[mt], ad + (SO_A2 - SO_A1));
            }
#pragma unroll
            for (int ng = 0; ng < 2; ++ng) {
                int rowb = wn*32 + ng*16 + (lane & 7) + ((lane >> 4) << 3);
                int colb = (kb + ((lane >> 3) & 1)) ^ (rowb & 7);
                uint32_t bd = sB1 + rowb*128 + colb*16;
                ldsm4(b1f[ng], bd);
                ldsm4(b2f[ng], bd + (SO_B2 - SO_B1));
            }
#pragma unroll
            for (int mt = 0; mt < 2; ++mt)
#pragma unroll
                for (int ng = 0; ng < 2; ++ng)
#pragma unroll
                    for (int hf = 0; hf < 2; ++hf) {
                        float* c = acc[mt][ng*2 + hf];
                        uint32_t* ch = acch[mt][ng*2 + hf];
                        mma16816(c, a1f[mt], &b1f[ng][hf*2]);
                        mma16816h(ch, a1f[mt], &b2f[ng][hf*2]);
                        mma16816h(ch, a2f[mt], &b1f[ng][hf*2]);
                    }
        }
    };

    if (is_prod) produce(0, 0);
    __syncthreads();
#pragma unroll 1
    for (int ch = 0; ch < NCH; ++ch) {
        if (is_prod) {
            if (ch + 1 < NCH) produce(ch + 1, (ch + 1) & 1);
        } else {
            comp_chunk(ch & 1);
        }
        __syncthreads();
    }

    // ---- dump accumulators (+ scaled corrections) to ls[128][68] (consumers) ----
    float* ls = reinterpret_cast<float*>(smem + SO_LS);
    if (tid < 256) {
#pragma unroll
        for (int mt = 0; mt < 2; ++mt)
#pragma unroll
            for (int nt = 0; nt < 4; ++nt) {
                int row = wm*32 + mt*16 + (lane >> 2);
                int col = wn*32 + nt*8 + (lane & 3)*2;
                __half2 hc0 = *reinterpret_cast<__half2*>(&acch[mt][nt][0]);
                __half2 hc1 = *reinterpret_cast<__half2*>(&acch[mt][nt][1]);
                float2 c01 = __half22float2(hc0);
                float2 c23 = __half22float2(hc1);
                *reinterpret_cast<float2*>(ls + row*68 + col) =
                    make_float2(acc[mt][nt][0] + c01.x*CORR_SCALE,
                                acc[mt][nt][1] + c01.y*CORR_SCALE);
                *reinterpret_cast<float2*>(ls + (row + 8)*68 + col) =
                    make_float2(acc[mt][nt][2] + c23.x*CORR_SCALE,
                                acc[mt][nt][3] + c23.y*CORR_SCALE);
            }
    }
    __syncthreads();

    // ---- per-token epilogue (warps 0-3, 1 token per thread) ----
    float* bs = reinterpret_cast<float*>(smem + SO_BS);
    float* zred = reinterpret_cast<float*>(smem + SO_ZRED);
    float lg[64];
    float zl = 0.f;
    if (tid < 128) {
        const int t = tid;
#pragma unroll
        for (int e = 0; e < 64; ++e) lg[e] = ls[t*68 + e] + bs[e];

        float mx = lg[0];
#pragma unroll
        for (int e = 1; e < 64; ++e) mx = fmaxf(mx, lg[e]);
        float ssum = 0.f;
#pragma unroll
        for (int e = 0; e < 64; ++e) { float p = expf(lg[e] - mx); lg[e] = p; ssum += p; }
        float logz = mx + logf(ssum);
        float inv = 1.f / ssum;
#pragma unroll
        for (int e = 0; e < 64; ++e) lg[e] *= inv;

        float p0 = -1.f, p1 = -1.f; int i0 = 0, i1 = 0;
#pragma unroll
        for (int e = 0; e < 64; ++e) {
            float v = lg[e];
            if (v > p0) { p1 = p0; i1 = i0; p0 = v; i0 = e; }
            else if (v > p1) { p1 = v; i1 = e; }
        }
        const int token = tok0 + t;
        g_gate0[token] = p0; g_gate1[token] = p1;
        g_e0[token] = i0;    g_e1[token] = i1;
        const int grp = token >> 12;
        atomicAdd(&g_cnt[grp*E + i0], 1);
        atomicAdd(&g_cnt[grp*E + i1], 1);
        zl = logz * logz;
    }
    __syncthreads();

    if (tid < 128) {
        float* row = ls + tid*68;
#pragma unroll
        for (int c = 0; c < 16; ++c)
            *reinterpret_cast<float4*>(row + c*4) =
                make_float4(lg[4*c], lg[4*c+1], lg[4*c+2], lg[4*c+3]);
#pragma unroll
        for (int o = 16; o; o >>= 1) zl += __shfl_xor_sync(0xffffffffu, zl, o);
        if (lane == 0) zred[wid] = zl;
    }
    __syncthreads();

    // coalesced prob copy-out + deterministic per-CTA per-expert sums (256 thr)
    if (tid < 256) {
        float* P = out + P_OFF + (size_t)tok0*64;
        float s = 0.f;
        for (int k = tid; k < TM*64; k += 256) {
            float v = ls[(k >> 6)*68 + (k & 63)];
            P[k] = v;
            s += v;
        }
        psums[tid >> 6][tid & 63] = s;
    }
    __syncthreads();
    if (tid < 64)
        g_psum2[blockIdx.x*64 + tid] =
            psums[0][tid] + psums[1][tid] + psums[2][tid] + psums[3][tid];

    if (tid == 0)
        g_zpart[blockIdx.x] = zred[0] + zred[1] + zred[2] + zred[3];
}

// ---------------- K2: stable rank by gate0 (descending), split-loop ----------------
__global__ __launch_bounds__(256) void k2_rank() {
    __shared__ __align__(16) float gs[T];
    const int tid = threadIdx.x;
    const int grp = blockIdx.y;
    for (int i = tid; i < T; i += 256) gs[i] = g_gate0[grp*T + i];
    __syncthreads();
    const int t = blockIdx.x * 256 + tid;
    const float gi = gs[t];
    const int tb = t >> 2;
    const float4* gv = reinterpret_cast<const float4*>(gs);
    int rank = 0;
#pragma unroll 4
    for (int j = 0; j < tb; ++j) {        // indices < t: count >=
        float4 v = gv[j];
        rank += (v.x >= gi) + (v.y >= gi) + (v.z >= gi) + (v.w >= gi);
    }
    {   // boundary block containing t
        float4 v = gv[tb];
        int j4 = tb*4;
        rank += (v.x > gi) || (v.x == gi && (j4    ) < t);
        rank += (v.y > gi) || (v.y == gi && (j4 + 1) < t);
        rank += (v.z > gi) || (v.z == gi && (j4 + 2) < t);
        rank += (v.w > gi) || (v.w == gi && (j4 + 3) < t);
    }
#pragma unroll 4
    for (int j = tb + 1; j < T/4; ++j) {  // indices > t: strict
        float4 v = gv[j];
        rank += (v.x > gi) + (v.y > gi) + (v.z > gi) + (v.w > gi);
    }
    int e0 = g_e0[grp*T + t], e1 = g_e1[grp*T + t];
    g_sorted[grp*T + rank] = t | (e0 << 12) | (e1 << 18);
}

// ---------------- K3a: priorities via PARALLEL decoupled lookback, 64 CTAs ----------------
__global__ __launch_bounds__(1024) void k3a_prio() {
    __shared__ int whist[32][64];
    __shared__ int wexc[32][64];
    __shared__ int lk[8][64];
    __shared__ int sbase[64];

    const int g = blockIdx.x >> 3, s = blockIdx.x & 7;
    const int tid = threadIdx.x;
    const int w = tid >> 5, lane = tid & 31;
    const unsigned lt = (1u << lane) - 1u;

    whist[w][lane] = 0;
    whist[w][lane + 32] = 0;

    const int p = s*1024 + tid;                 // global sequence position
    const int pk = g_sorted[g*T + (p & (T-1))];
    const int tok = pk & 4095;
    const int e = (s < 4) ? ((pk >> 12) & 63) : ((pk >> 18) & 63);
    __syncwarp();

    unsigned m = __match_any_sync(0xffffffffu, e);
    int lrank = __popc(m & lt);
    if (lane == (__ffs(m) - 1)) whist[w][e] = __popc(m);
    __syncthreads();

    // warp-parallel exclusive scan over warps, per expert (warp <-> expert, 2 passes)
#pragma unroll
    for (int pass = 0; pass < 2; ++pass) {
        int ee = w + pass*32;                   // this warp handles expert ee
        int val = whist[lane][ee];
        int incl = val;
#pragma unroll
        for (int o = 1; o < 32; o <<= 1) {
            int n = __shfl_up_sync(0xffffffffu, incl, o);
            if (lane >= o) incl += n;
        }
        wexc[lane][ee] = incl - val;
        if (lane == 31) g_seghist[blockIdx.x*64 + ee] = incl;  // segment total
    }
    __syncthreads();
    if (tid == 0) {
        __threadfence();
        atomicExch(&g_segflag[blockIdx.x], 1);
    }

    // PARALLEL lookback: 8 spin-groups, one per predecessor slot
    if (tid < 512) {
        const int sp = tid >> 6, ee = tid & 63;
        int val = 0;
        if (sp < s) {
            volatile int* fl = &g_segflag[g*8 + sp];
            while (*fl == 0) { }
            __threadfence();
            val = *((volatile int*)&g_seghist[(g*8 + sp)*64 + ee]);
        }
        lk[sp][ee] = val;
    }
    __syncthreads();
    if (tid < 64) {
        int base = 0;
#pragma unroll
        for (int sp = 0; sp < 8; ++sp) base += lk[sp][tid];
        sbase[tid] = base;
    }
    __syncthreads();

    int prio = sbase[e] + wexc[w][e] + lrank;
    if (s < 4) g_prio0[g*T + tok] = prio;
    else       g_prio1[g*T + tok] = prio;
}

// ---------------- K3b: dispatch/combine outputs + final scalars (block 0) ----------------
__global__ __launch_bounds__(256) void k3b_out(float* __restrict__ out,
                                               const int* __restrict__ capPtr) {
    const int idx = blockIdx.x * 256 + threadIdx.x;   // one token per thread
    const int cap = capPtr ? *capPtr : 160;
    int e0 = g_e0[idx], e1 = g_e1[idx];
    int pr0 = g_prio0[idx], pr1 = g_prio1[idx];
    float gt0 = g_gate0[idx], gt1 = g_gate1[idx];
    float4 d = make_float4((float)e0, (float)pr0, (float)e1, (float)pr1);
    reinterpret_cast<float4*>(out + DI_OFF)[idx] = d;
    float2 cc = make_float2(pr0 < cap ? gt0 : 0.f, pr1 < cap ? gt1 : 0.f);
    reinterpret_cast<float2*>(out + CW_OFF)[idx] = cc;

    // block 0: final scalars (deterministic; inputs ready since k1)
    if (blockIdx.x == 0) {
        __shared__ float redA[8], redZ[8];
        const int tid = threadIdx.x;
        const int g4 = tid >> 6, e = tid & 63;
        float a = 0.f;
#pragma unroll
        for (int half = 0; half < 2; ++half) {
            int gg = g4 + half*4;
            float ps = 0.f;
#pragma unroll
            for (int c = 0; c < 32; ++c) ps += g_psum2[(gg*32 + c)*64 + e];
            a += (float)g_cnt[gg*E + e] * ps;
        }
        float z = g_zpart[tid];   // NCTA == 256
#pragma unroll
        for (int o = 16; o; o >>= 1) {
            a += __shfl_xor_sync(0xffffffffu, a, o);
            z += __shfl_xor_sync(0xffffffffu, z, o);
        }
        if ((tid & 31) == 0) { redA[tid >> 5] = a; redZ[tid >> 5] = z; }
        __syncthreads();
        if (tid == 0) {
            float sa = 0.f, sz = 0.f;
#pragma unroll
            for (int i = 0; i < 8; ++i) { sa += redA[i]; sz += redZ[i]; }
            out[AUX_OFF] = sa * (1.f / 2097152.f);
            out[Z_OFF]   = sz * (1.f / 32768.f);
        }
    }
}

extern "C" void kernel_launch(void* const* d_in, const int* in_sizes, int n_in,
                              void* d_out, int out_size) {
    const float* X = (const float*)d_in[0];
    const float* W = (const float*)d_in[1];
    const float* B = (const float*)d_in[2];
    const int* cap = (n_in > 3) ? (const int*)d_in[3] : nullptr;
    float* out = (float*)d_out;

    cudaFuncSetAttribute(k1_gemm, cudaFuncAttributeMaxDynamicSharedMemorySize, SMEM_TOTAL);

    k0_prep<<<128, 256>>>(W);
    k1_gemm<<<NCTA, NTHR, SMEM_TOTAL>>>(X, B, out);
    k2_rank<<<dim3(16, 8), 256>>>();
    k3a_prio<<<64, 1024>>>();
    k3b_out<<<GT/256, 256>>>(out, cap);
}

// round 17
// speedup vs baseline: 1.2658x; 1.2658x over previous
#include <cuda_runtime.h>
#include <cuda_fp16.h>
#include <cstdint>

// Problem constants
#define G 8
#define T 4096
#define H 2048
#define E 64
#define GT (G*T)              // 32768 tokens

// Output layout (float32, concatenated in reference return order)
#define DI_OFF 0              // dispatch_indices [G,T,2,2] -> 131072
#define CW_OFF 131072         // combine_weights  [G,T,2]   -> 65536
#define AUX_OFF 196608        // scalar
#define P_OFF 196609          // router_probs [G,T,64] -> 2097152
#define Z_OFF 2293761         // scalar

// K1 tiling
#define KB 64                 // k-elems per chunk (128B fp16 rows)
#define NCH (H/KB)            // 32 chunks
#define TM 128                // tokens per CTA
#define NCTA (GT/TM)          // 256 CTAs

// K1 dynamic smem byte offsets
#define SO_BS   0                       // bias, 64 floats
#define SO_ZRED 256                     // 4 floats
#define SO_A1   1024                    // x hi limb: 2 bufs x 16KB
#define SO_A2   (SO_A1 + 32768)         // x lo limb (scaled 2^11): 2 bufs x 16KB
#define SO_B1   (SO_A2 + 32768)         // w hi limb: 2 bufs x 8KB
#define SO_B2   (SO_B1 + 16384)         // w lo limb (scaled 2^11): 2 bufs x 8KB
#define SMEM_TOTAL (SO_B2 + 16384)      // 99328 bytes
#define SO_LS   1024                    // epilogue overlay: 128 x 68 floats

#define CORR_SCALE (1.0f/2048.0f)

// -------- scratch (device globals; no allocation allowed) --------
__device__ float g_gate0[GT];
__device__ float g_gate1[GT];
__device__ int   g_e0[GT];
__device__ int   g_e1[GT];
__device__ int   g_sorted[GT];   // packed: tok | e0<<12 | e1<<18 (rank order)
__device__ int   g_prio0[GT];
__device__ int   g_prio1[GT];
__device__ float g_zpart[NCTA];
__device__ int   g_cnt[G*E];
__device__ float g_psum2[NCTA*E];   // per-CTA prob sums (deterministic)
__device__ __half g_w1[E*H];   // W^T hi limb [expert][k]
__device__ __half g_w2[E*H];   // W^T lo limb, scaled by 2^11
__device__ int   g_seghist[64*64];  // per (group,segment) expert totals
__device__ int   g_segflag[64];     // seghist-ready flags
__device__ int   g_k2done[G];       // per-group rank-phase arrival counters
__device__ int   g_priodone[64];    // per-segment prio-written flags

__device__ __forceinline__ uint32_t smem_u32(const void* p) {
    uint32_t a;
    asm("{ .reg .u64 t; cvta.to.shared.u64 t, %1; cvt.u32.u64 %0, t; }"
        : "=r"(a) : "l"(p));
    return a;
}
__device__ __forceinline__ void ldsm4(uint32_t* r, uint32_t a) {
    asm volatile("ldmatrix.sync.aligned.m8n8.x4.shared.b16 {%0,%1,%2,%3}, [%4];"
        : "=r"(r[0]), "=r"(r[1]), "=r"(r[2]), "=r"(r[3]) : "r"(a));
}
__device__ __forceinline__ void mma16816(float* c, const uint32_t* a, const uint32_t* b) {
    asm volatile("mma.sync.aligned.m16n8k16.row.col.f32.f16.f16.f32 "
        "{%0,%1,%2,%3}, {%4,%5,%6,%7}, {%8,%9}, {%0,%1,%2,%3};"
        : "+f"(c[0]), "+f"(c[1]), "+f"(c[2]), "+f"(c[3])
        : "r"(a[0]), "r"(a[1]), "r"(a[2]), "r"(a[3]), "r"(b[0]), "r"(b[1]));
}
__device__ __forceinline__ void mma16816h(uint32_t* c, const uint32_t* a, const uint32_t* b) {
    asm volatile("mma.sync.aligned.m16n8k16.row.col.f16.f16.f16.f16 "
        "{%0,%1}, {%2,%3,%4,%5}, {%6,%7}, {%0,%1};"
        : "+r"(c[0]), "+r"(c[1])
        : "r"(a[0]), "r"(a[1]), "r"(a[2]), "r"(a[3]), "r"(b[0]), "r"(b[1]));
}
__device__ __forceinline__ uint32_t h2u(__half2 h) {
    return *reinterpret_cast<uint32_t*>(&h);
}
__device__ __forceinline__ void cp16(uint32_t dst, const void* src) {
    asm volatile("cp.async.cg.shared.global [%0], [%1], 16;"
        :: "r"(dst), "l"(src) : "memory");
}

// ---------------- K0: zero counters/flags + preconvert W^T into fp16 limbs ----------------
__global__ __launch_bounds__(256) void k0_prep(const float* __restrict__ W) {
    int gidx = blockIdx.x * 256 + threadIdx.x;     // 128 CTAs -> 32768 threads
    if (gidx < G*E) g_cnt[gidx] = 0;
    if (gidx >= 512 && gidx < 576) g_segflag[gidx - 512] = 0;
    if (gidx >= 576 && gidx < 584) g_k2done[gidx - 576] = 0;
    if (gidx >= 584 && gidx < 648) g_priodone[gidx - 584] = 0;
    // H*16 float4 granules: k = gidx>>4, experts 4q..4q+3
    int k = gidx >> 4, q = gidx & 15;
    float4 v = reinterpret_cast<const float4*>(W)[gidx];
    float xs[4] = {v.x, v.y, v.z, v.w};
#pragma unroll
    for (int j = 0; j < 4; ++j) {
        int e = 4*q + j;
        __half hi = __float2half_rn(xs[j]);
        float hf = __half2float(hi);
        __half lo = __float2half_rn((xs[j] - hf) * 2048.0f);  // pre-scaled limb
        g_w1[e*H + k] = hi;
        g_w2[e*H + k] = lo;
    }
}

// ---------------- K1: mma.sync GEMM (2-limb fp16, f16-accum corrections) ----------------
// 256 threads (8 warps: 4 M x 2 N), 128 tokens/CTA, chunks of K=64.
// X limbs split in-registers -> STS; W limbs copied gmem->smem via cp.async,
// issued right after the barrier so the copy overlaps the whole comp(ch).
__global__ __launch_bounds__(256, 2) void k1_gemm(
    const float* __restrict__ X, const float* __restrict__ Bv,
    float* __restrict__ out)
{
    extern __shared__ __align__(16) char smem[];
    __shared__ float psums[4][64];
    const uint32_t sb = smem_u32(smem);
    const int tid = threadIdx.x;
    const int wid = tid >> 5, lane = tid & 31;
    const int wm = wid >> 1, wn = wid & 1;
    const int tok0 = blockIdx.x * TM;

    if (tid < 64) *reinterpret_cast<float*>(smem + SO_BS + tid*4) = Bv[tid];

    float acc[2][4][4];
    uint32_t acch[2][4][2];
#pragma unroll
    for (int mt = 0; mt < 2; ++mt)
#pragma unroll
        for (int nt = 0; nt < 4; ++nt) {
#pragma unroll
            for (int i = 0; i < 4; ++i) acc[mt][nt][i] = 0.f;
            acch[mt][nt][0] = 0u; acch[mt][nt][1] = 0u;
        }

    float4 xv[8];

    auto ldg_chunk = [&](int ch) {
        const int hc = ch * KB;
#pragma unroll
        for (int it = 0; it < 8; ++it) {
            int idx = it*256 + tid, row = idx >> 4, q = idx & 15;
            xv[it] = *reinterpret_cast<const float4*>(
                X + (size_t)(tok0 + row)*H + hc + q*4);
        }
    };

    // W limbs: gmem -> smem via cp.async (no conversion needed)
    auto cpb_chunk = [&](int ch, int buf) {
        const int hc = ch * KB;
        const uint32_t B1 = sb + SO_B1 + buf*8192;
        const uint32_t B2 = sb + SO_B2 + buf*8192;
#pragma unroll
        for (int it = 0; it < 2; ++it) {
            int idx = it*256 + tid, e = idx >> 3, g = idx & 7;
            int offs = e*128 + ((g ^ (e & 7)) << 4);
            cp16(B1 + offs, g_w1 + (size_t)e*H + hc + g*8);
            cp16(B2 + offs, g_w2 + (size_t)e*H + hc + g*8);
        }
        asm volatile("cp.async.commit_group;" ::: "memory");
    };

    auto sts_chunk = [&](int buf) {
        char* A1 = smem + SO_A1 + buf*16384;
        char* A2 = smem + SO_A2 + buf*16384;
#pragma unroll
        for (int it = 0; it < 8; ++it) {
            int idx = it*256 + tid, row = idx >> 4, q = idx & 15;
            float4 v = xv[it];
            __half2 h01 = __floats2half2_rn(v.x, v.y);
            __half2 h23 = __floats2half2_rn(v.z, v.w);
            float2 f01 = __half22float2(h01);
            float2 f23 = __half22float2(h23);
            __half2 l01 = __floats2half2_rn((v.x - f01.x)*2048.f, (v.y - f01.y)*2048.f);
            __half2 l23 = __floats2half2_rn((v.z - f23.x)*2048.f, (v.w - f23.y)*2048.f);
            int offs = row*128 + ((((q >> 1) ^ (row & 7)) << 4) | ((q & 1) << 3));
            *reinterpret_cast<uint2*>(A1 + offs) = make_uint2(h2u(h01), h2u(h23));
            *reinterpret_cast<uint2*>(A2 + offs) = make_uint2(h2u(l01), h2u(l23));
        }
    };

    auto comp_chunk = [&](int buf) {
        const uint32_t sA1 = sb + SO_A1 + buf*16384;
        const uint32_t sB1 = sb + SO_B1 + buf*8192;
#pragma unroll
        for (int ks = 0; ks < 4; ++ks) {
            const int kb = ks*2;
            uint32_t a1f[2][4], a2f[2][4], b1f[2][4], b2f[2][4];
#pragma unroll
            for (int mt = 0; mt < 2; ++mt) {
                int row = wm*32 + mt*16 + (lane & 15);
                int col = (kb + (lane >> 4)) ^ (row & 7);
                uint32_t ad = sA1 + row*128 + col*16;
                ldsm4(a1f[mt], ad);
                ldsm4(a2f[mt], ad + (SO_A2 - SO_A1));
            }
#pragma unroll
            for (int ng = 0; ng < 2; ++ng) {
                int rowb = wn*32 + ng*16 + (lane & 7) + ((lane >> 4) << 3);
                int colb = (kb + ((lane >> 3) & 1)) ^ (rowb & 7);
                uint32_t bd = sB1 + rowb*128 + colb*16;
                ldsm4(b1f[ng], bd);
                ldsm4(b2f[ng], bd + (SO_B2 - SO_B1));
            }
#pragma unroll
            for (int mt = 0; mt < 2; ++mt)
#pragma unroll
                for (int ng = 0; ng < 2; ++ng)
#pragma unroll
                    for (int hf = 0; hf < 2; ++hf) {
                        float* c = acc[mt][ng*2 + hf];
                        uint32_t* ch = acch[mt][ng*2 + hf];
                        mma16816(c, a1f[mt], &b1f[ng][hf*2]);
                        mma16816h(ch, a1f[mt], &b2f[ng][hf*2]);
                        mma16816h(ch, a2f[mt], &b1f[ng][hf*2]);
                    }
        }
    };

    ldg_chunk(0);
    cpb_chunk(0, 0);
    sts_chunk(0);
#pragma unroll 1
    for (int ch = 0; ch < NCH; ++ch) {
        if (ch + 1 < NCH) ldg_chunk(ch + 1);
        asm volatile("cp.async.wait_group 0;" ::: "memory");  // B(ch) complete
        __syncthreads();                  // all warps done comp(ch-1); A/B(ch) visible
        if (ch + 1 < NCH) cpb_chunk(ch + 1, (ch + 1) & 1);    // overlaps comp(ch)
        comp_chunk(ch & 1);
        if (ch + 1 < NCH) sts_chunk((ch + 1) & 1);
    }
    __syncthreads();   // all comp done; safe to overlay ls

    // ---- dump accumulators (+ scaled corrections) to ls[128][68] ----
    float* ls = reinterpret_cast<float*>(smem + SO_LS);
#pragma unroll
    for (int mt = 0; mt < 2; ++mt)
#pragma unroll
        for (int nt = 0; nt < 4; ++nt) {
            int row = wm*32 + mt*16 + (lane >> 2);
            int col = wn*32 + nt*8 + (lane & 3)*2;
            __half2 hc0 = *reinterpret_cast<__half2*>(&acch[mt][nt][0]);
            __half2 hc1 = *reinterpret_cast<__half2*>(&acch[mt][nt][1]);
            float2 c01 = __half22float2(hc0);
            float2 c23 = __half22float2(hc1);
            *reinterpret_cast<float2*>(ls + row*68 + col) =
                make_float2(acc[mt][nt][0] + c01.x*CORR_SCALE,
                            acc[mt][nt][1] + c01.y*CORR_SCALE);
            *reinterpret_cast<float2*>(ls + (row + 8)*68 + col) =
                make_float2(acc[mt][nt][2] + c23.x*CORR_SCALE,
                            acc[mt][nt][3] + c23.y*CORR_SCALE);
        }
    __syncthreads();

    // ---- per-token epilogue (warps 0-3, 1 token per thread) ----
    float* bs = reinterpret_cast<float*>(smem + SO_BS);
    float* zred = reinterpret_cast<float*>(smem + SO_ZRED);
    float lg[64];
    float zl = 0.f;
    if (tid < 128) {
        const int t = tid;
#pragma unroll
        for (int e = 0; e < 64; ++e) lg[e] = ls[t*68 + e] + bs[e];

        float mx = lg[0];
#pragma unroll
        for (int e = 1; e < 64; ++e) mx = fmaxf(mx, lg[e]);
        float ssum = 0.f;
#pragma unroll
        for (int e = 0; e < 64; ++e) { float p = expf(lg[e] - mx); lg[e] = p; ssum += p; }
        float logz = mx + logf(ssum);
        float inv = 1.f / ssum;
#pragma unroll
        for (int e = 0; e < 64; ++e) lg[e] *= inv;

        float p0 = -1.f, p1 = -1.f; int i0 = 0, i1 = 0;
#pragma unroll
        for (int e = 0; e < 64; ++e) {
            float v = lg[e];
            if (v > p0) { p1 = p0; i1 = i0; p0 = v; i0 = e; }
            else if (v > p1) { p1 = v; i1 = e; }
        }
        const int token = tok0 + t;
        g_gate0[token] = p0; g_gate1[token] = p1;
        g_e0[token] = i0;    g_e1[token] = i1;
        const int grp = token >> 12;
        atomicAdd(&g_cnt[grp*E + i0], 1);
        atomicAdd(&g_cnt[grp*E + i1], 1);
        zl = logz * logz;
    }
    __syncthreads();

    if (tid < 128) {
        float* row = ls + tid*68;
#pragma unroll
        for (int c = 0; c < 16; ++c)
            *reinterpret_cast<float4*>(row + c*4) =
                make_float4(lg[4*c], lg[4*c+1], lg[4*c+2], lg[4*c+3]);
#pragma unroll
        for (int o = 16; o; o >>= 1) zl += __shfl_xor_sync(0xffffffffu, zl, o);
        if (lane == 0) zred[wid] = zl;
    }
    __syncthreads();

    // coalesced prob copy-out + deterministic per-CTA per-expert sums
    float* P = out + P_OFF + (size_t)tok0*64;
    float s = 0.f;
    for (int k = tid; k < TM*64; k += 256) {
        float v = ls[(k >> 6)*68 + (k & 63)];
        P[k] = v;
        s += v;
    }
    psums[tid >> 6][tid & 63] = s;
    __syncthreads();
    if (tid < 64)
        g_psum2[blockIdx.x*64 + tid] =
            psums[0][tid] + psums[1][tid] + psums[2][tid] + psums[3][tid];

    if (tid == 0)
        g_zpart[blockIdx.x] = zred[0] + zred[1] + zred[2] + zred[3];
}

// ---------------- K23: fused rank + priorities + outputs ----------------
// Grid (16, 8) x 256 threads; all 128 CTAs co-resident (<=148 SMs) so cross-CTA
// spin-waits cannot deadlock.
// Phase A: CTA (c,g) ranks tokens c*256..c*256+255 of group g (split-loop).
// Phase B: CTAs c<8 compute segment priorities (decoupled lookback).
// Phase C: each CTA writes dispatch/combine for its 256 tokens; block (0,0)
// reduces the scalar losses.
__global__ __launch_bounds__(256) void k23(float* __restrict__ out,
                                           const int* __restrict__ capPtr) {
    __shared__ __align__(16) float gs[T];     // 16KB, phase A only
    __shared__ int wcnt[8][64];
    __shared__ int wexc[8][64];
    __shared__ int lk[8][64];
    __shared__ int sbase[64];
    __shared__ float redA[8], redZ[8];

    const int c = blockIdx.x, g = blockIdx.y;
    const int tid = threadIdx.x;
    const int w = tid >> 5, lane = tid & 31;
    const unsigned lt = (1u << lane) - 1u;

    // ======== Phase A: rank (split-loop, bit-identical semantics) ========
    for (int i = tid; i < T; i += 256) gs[i] = g_gate0[g*T + i];
    __syncthreads();
    {
        const int t = c*256 + tid;
        const float gi = gs[t];
        const int tb = t >> 2;
        const float4* gv = reinterpret_cast<const float4*>(gs);
        int rank = 0;
#pragma unroll 4
        for (int j = 0; j < tb; ++j) {
            float4 v = gv[j];
            rank += (v.x >= gi) + (v.y >= gi) + (v.z >= gi) + (v.w >= gi);
        }
        {
            float4 v = gv[tb];
            int j4 = tb*4;
            rank += (v.x > gi) || (v.x == gi && (j4    ) < t);
            rank += (v.y > gi) || (v.y == gi && (j4 + 1) < t);
            rank += (v.z > gi) || (v.z == gi && (j4 + 2) < t);
            rank += (v.w > gi) || (v.w == gi && (j4 + 3) < t);
        }
#pragma unroll 4
        for (int j = tb + 1; j < T/4; ++j) {
            float4 v = gv[j];
            rank += (v.x > gi) + (v.y > gi) + (v.z > gi) + (v.w > gi);
        }
        int e0 = g_e0[g*T + t], e1 = g_e1[g*T + t];
        g_sorted[g*T + rank] = t | (e0 << 12) | (e1 << 18);
    }
    __threadfence();
    __syncthreads();
    if (tid == 0) atomicAdd(&g_k2done[g], 1);

    // ======== Phase B: segment priorities (CTAs c<8) ========
    if (c < 8) {
        const int s = c;
        if (tid == 0) { while (atomicAdd(&g_k2done[g], 0) < 16) { } }
        __syncthreads();

        wcnt[w][lane] = 0;
        wcnt[w][lane + 32] = 0;

        int toks[4], es[4], offs[4];
#pragma unroll
        for (int i = 0; i < 4; ++i) {
            int p = s*1024 + w*128 + i*32 + lane;
            int pk = g_sorted[g*T + (p & (T-1))];
            toks[i] = pk & 4095;
            es[i] = (s < 4) ? ((pk >> 12) & 63) : ((pk >> 18) & 63);
            unsigned m = __match_any_sync(0xffffffffu, es[i]);
            int lrank = __popc(m & lt);
            offs[i] = wcnt[w][es[i]] + lrank;
            __syncwarp();
            if (lane == (__ffs(m) - 1)) wcnt[w][es[i]] += __popc(m);
            __syncwarp();
        }
        __syncthreads();

        if (tid < 64) {
            int run = 0;
#pragma unroll
            for (int ww = 0; ww < 8; ++ww) { wexc[ww][tid] = run; run += wcnt[ww][tid]; }
            g_seghist[(g*8 + s)*64 + tid] = run;
            __threadfence();
        }
        __syncthreads();
        if (tid == 0) atomicExch(&g_segflag[g*8 + s], 1);

        // parallel lookback: 4 predecessor slots per rep, 2 reps
#pragma unroll
        for (int rep = 0; rep < 2; ++rep) {
            int sp = (tid >> 6) + rep*4, ee = tid & 63;
            int val = 0;
            if (sp < s) {
                volatile int* fl = &g_segflag[g*8 + sp];
                while (*fl == 0) { }
                __threadfence();
                val = *((volatile int*)&g_seghist[(g*8 + sp)*64 + ee]);
            }
            lk[sp][ee] = val;
        }
        __syncthreads();
        if (tid < 64) {
            int base = 0;
#pragma unroll
            for (int sp = 0; sp < 8; ++sp) base += lk[sp][tid];
            sbase[tid] = base;
        }
        __syncthreads();

#pragma unroll
        for (int i = 0; i < 4; ++i) {
            int prio = sbase[es[i]] + wexc[w][es[i]] + offs[i];
            if (s < 4) g_prio0[g*T + toks[i]] = prio;
            else       g_prio1[g*T + toks[i]] = prio;
        }
        __threadfence();
        __syncthreads();
        if (tid == 0) atomicExch(&g_priodone[g*8 + s], 1);
    }

    // ======== Phase C: outputs for this CTA's 256 tokens ========
    if (tid < 8) {
        volatile int* fl = &g_priodone[g*8 + tid];
        while (*fl == 0) { }
    }
    __syncthreads();
    __threadfence();
    {
        const int idx = g*T + c*256 + tid;
        const int cap = capPtr ? *capPtr : 160;
        int e0 = g_e0[idx], e1 = g_e1[idx];
        int pr0 = g_prio0[idx], pr1 = g_prio1[idx];
        float gt0 = g_gate0[idx], gt1 = g_gate1[idx];
        float4 d = make_float4((float)e0, (float)pr0, (float)e1, (float)pr1);
        reinterpret_cast<float4*>(out + DI_OFF)[idx] = d;
        float2 cc = make_float2(pr0 < cap ? gt0 : 0.f, pr1 < cap ? gt1 : 0.f);
        reinterpret_cast<float2*>(out + CW_OFF)[idx] = cc;
    }

    // ======== scalars: block (0,0) ========
    if (c == 0 && g == 0) {
        const int g4 = tid >> 6, e = tid & 63;
        float a = 0.f;
#pragma unroll
        for (int half = 0; half < 2; ++half) {
            int gg = g4 + half*4;
            float ps = 0.f;
#pragma unroll
            for (int cc2 = 0; cc2 < 32; ++cc2) ps += g_psum2[(gg*32 + cc2)*64 + e];
            a += (float)g_cnt[gg*E + e] * ps;
        }
        float z = g_zpart[tid];   // NCTA == 256
#pragma unroll
        for (int o = 16; o; o >>= 1) {
            a += __shfl_xor_sync(0xffffffffu, a, o);
            z += __shfl_xor_sync(0xffffffffu, z, o);
        }
        if (lane == 0) { redA[w] = a; redZ[w] = z; }
        __syncthreads();
        if (tid == 0) {
            float sa = 0.f, sz = 0.f;
#pragma unroll
            for (int i = 0; i < 8; ++i) { sa += redA[i]; sz += redZ[i]; }
            out[AUX_OFF] = sa * (1.f / 2097152.f);
            out[Z_OFF]   = sz * (1.f / 32768.f);
        }
    }
}

extern "C" void kernel_launch(void* const* d_in, const int* in_sizes, int n_in,
                              void* d_out, int out_size) {
    const float* X = (const float*)d_in[0];
    const float* W = (const float*)d_in[1];
    const float* B = (const float*)d_in[2];
    const int* cap = (n_in > 3) ? (const int*)d_in[3] : nullptr;
    float* out = (float*)d_out;

    cudaFuncSetAttribute(k1_gemm, cudaFuncAttributeMaxDynamicSharedMemorySize, SMEM_TOTAL);

    k0_prep<<<128, 256>>>(W);
    k1_gemm<<<NCTA, 256, SMEM_TOTAL>>>(X, B, out);
    k23<<<dim3(16, 8), 256>>>(out, cap);
}